// round 1
// baseline (speedup 1.0000x reference)
#include <cuda_runtime.h>

// Shapes (fixed for this problem)
#define B_ 32
#define S_ 128
#define E_ 512
#define F_ 2048
#define KT 16        // K-tile depth
#define KSPLIT 4     // split-K for GEMM2

// Scratch (device globals: allocation-free)
// g_H layout: [s][f][b]  (b contiguous -> GEMM2 A-tile loads are coalesced)
__device__ float g_H[(size_t)S_ * F_ * B_];
// g_Yp layout: [kp][s][b][e] (e contiguous -> LN kernel reads vectorized)
__device__ float g_Yp[(size_t)KSPLIT * S_ * B_ * E_];

// ---------------------------------------------------------------------------
// GEMM1: H[s][f][b] = sum_e x[b][s][e] * W1[s][e][f] + b1[s][f]
// grid (F_/512, S_), 256 threads. CTA tile: M=32 (b), N=512 (f), K=E_=512.
// Thread tile 8x8 (tm in 0..3 covers 32 m, tn in 0..63 covers 512 n).
// ---------------------------------------------------------------------------
__global__ __launch_bounds__(256, 2)
void gemm1_kernel(const float* __restrict__ x,
                  const float* __restrict__ W1,
                  const float* __restrict__ b1)
{
    __shared__ float As[KT][B_];      // [k][m]
    __shared__ float Bs[KT][512];     // [k][n]

    const int s   = blockIdx.y;
    const int n0  = blockIdx.x * 512;
    const int tid = threadIdx.x;
    const int tm  = tid >> 6;   // 0..3  -> m base tm*8
    const int tn  = tid & 63;   // 0..63 -> n base tn*8

    float acc[8][8];
#pragma unroll
    for (int i = 0; i < 8; i++)
#pragma unroll
        for (int j = 0; j < 8; j++) acc[i][j] = 0.0f;

    for (int kt = 0; kt < E_ / KT; kt++) {
        const int e0 = kt * KT;

        // Load A tile: x[m][s][e0+k], transpose into As[k][m]. 512 floats.
        if (tid < 128) {
            const int m  = tid >> 2;
            const int k4 = (tid & 3) * 4;
            const float4 v = *(const float4*)&x[((size_t)m * S_ + s) * E_ + e0 + k4];
            As[k4 + 0][m] = v.x;
            As[k4 + 1][m] = v.y;
            As[k4 + 2][m] = v.z;
            As[k4 + 3][m] = v.w;
        }
        // Load B tile: W1[s][e0+row][n0 + c]. 16x512 floats = 2048 float4.
#pragma unroll
        for (int i = 0; i < 8; i++) {
            const int idx = i * 256 + tid;     // 0..2047
            const int row = idx >> 7;          // /128
            const int c4  = (idx & 127) * 4;
            *(float4*)&Bs[row][c4] =
                *(const float4*)&W1[((size_t)s * E_ + e0 + row) * F_ + n0 + c4];
        }
        __syncthreads();

#pragma unroll
        for (int k = 0; k < KT; k++) {
            float a[8], b[8];
#pragma unroll
            for (int i = 0; i < 8; i++) a[i] = As[k][tm * 8 + i];
#pragma unroll
            for (int j = 0; j < 8; j++) b[j] = Bs[k][tn * 8 + j];
#pragma unroll
            for (int i = 0; i < 8; i++)
#pragma unroll
                for (int j = 0; j < 8; j++) acc[i][j] += a[i] * b[j];
        }
        __syncthreads();
    }

    // Epilogue: + b1, store to g_H[s][n][m] (m contiguous).
#pragma unroll
    for (int j = 0; j < 8; j++) {
        const int n  = n0 + tn * 8 + j;
        const float bb = b1[(size_t)s * F_ + n];
        float4 v0, v1;
        v0.x = acc[0][j] + bb; v0.y = acc[1][j] + bb;
        v0.z = acc[2][j] + bb; v0.w = acc[3][j] + bb;
        v1.x = acc[4][j] + bb; v1.y = acc[5][j] + bb;
        v1.z = acc[6][j] + bb; v1.w = acc[7][j] + bb;
        float* dst = &g_H[((size_t)s * F_ + n) * B_ + tm * 8];
        *(float4*)(dst)     = v0;
        *(float4*)(dst + 4) = v1;
    }
}

// ---------------------------------------------------------------------------
// GEMM2 (split-K): Yp[kp][s][b][e] = sum_{f in kp-slice} H[s][f][b]*W2[s][f][e]
// grid (S_, KSPLIT), 256 threads. CTA tile: M=32 (b), N=512 (e), K=512 (f-slice)
// ---------------------------------------------------------------------------
__global__ __launch_bounds__(256, 2)
void gemm2_kernel(const float* __restrict__ W2)
{
    __shared__ float As[KT][B_];      // [k][m]
    __shared__ float Bs[KT][E_];      // [k][n]

    const int s   = blockIdx.x;
    const int kp  = blockIdx.y;
    const int f0b = kp * (F_ / KSPLIT);   // 512-wide K slice
    const int tid = threadIdx.x;
    const int tm  = tid >> 6;
    const int tn  = tid & 63;

    float acc[8][8];
#pragma unroll
    for (int i = 0; i < 8; i++)
#pragma unroll
        for (int j = 0; j < 8; j++) acc[i][j] = 0.0f;

    for (int kt = 0; kt < (F_ / KSPLIT) / KT; kt++) {
        const int f0 = f0b + kt * KT;

        // A tile from g_H[s][f0+row][m] — m contiguous, fully coalesced.
        if (tid < 128) {
            const int row = tid >> 3;           // 16 rows
            const int c4  = (tid & 7) * 4;      // 8 float4 per 32-wide row
            *(float4*)&As[row][c4] =
                *(const float4*)&g_H[((size_t)s * F_ + f0 + row) * B_ + c4];
        }
        // B tile: W2[s][f0+row][c]. 16x512 floats.
#pragma unroll
        for (int i = 0; i < 8; i++) {
            const int idx = i * 256 + tid;
            const int row = idx >> 7;
            const int c4  = (idx & 127) * 4;
            *(float4*)&Bs[row][c4] =
                *(const float4*)&W2[((size_t)s * F_ + f0 + row) * E_ + c4];
        }
        __syncthreads();

#pragma unroll
        for (int k = 0; k < KT; k++) {
            float a[8], b[8];
#pragma unroll
            for (int i = 0; i < 8; i++) a[i] = As[k][tm * 8 + i];
#pragma unroll
            for (int j = 0; j < 8; j++) b[j] = Bs[k][tn * 8 + j];
#pragma unroll
            for (int i = 0; i < 8; i++)
#pragma unroll
                for (int j = 0; j < 8; j++) acc[i][j] += a[i] * b[j];
        }
        __syncthreads();
    }

    // Store partial: Yp[kp][s][m][e], e contiguous per m.
#pragma unroll
    for (int i = 0; i < 8; i++) {
        const int m = tm * 8 + i;
        float4 v0, v1;
        v0.x = acc[i][0]; v0.y = acc[i][1]; v0.z = acc[i][2]; v0.w = acc[i][3];
        v1.x = acc[i][4]; v1.y = acc[i][5]; v1.z = acc[i][6]; v1.w = acc[i][7];
        float* dst = &g_Yp[(((size_t)kp * S_ + s) * B_ + m) * E_ + tn * 8];
        *(float4*)(dst)     = v0;
        *(float4*)(dst + 4) = v1;
    }
}

// ---------------------------------------------------------------------------
// LN kernel: y = sum_kp Yp + b2 + x ; out = LayerNorm(y)*gamma + beta
// grid = B_*S_ blocks, 128 threads, 4 elems (1 float4) per thread.
// ---------------------------------------------------------------------------
__global__ __launch_bounds__(128)
void ln_kernel(const float* __restrict__ x,
               const float* __restrict__ b2,
               const float* __restrict__ gamma,
               const float* __restrict__ beta,
               float* __restrict__ out)
{
    const int blk = blockIdx.x;
    const int b   = blk >> 7;      // /S_
    const int s   = blk & (S_ - 1);
    const int tid = threadIdx.x;
    const int e   = tid * 4;

    float4 y = *(const float4*)&g_Yp[(((size_t)0 * S_ + s) * B_ + b) * E_ + e];
#pragma unroll
    for (int kp = 1; kp < KSPLIT; kp++) {
        const float4 p = *(const float4*)&g_Yp[(((size_t)kp * S_ + s) * B_ + b) * E_ + e];
        y.x += p.x; y.y += p.y; y.z += p.z; y.w += p.w;
    }
    {
        const float4 bb = *(const float4*)&b2[(size_t)s * E_ + e];
        const float4 xr = *(const float4*)&x[((size_t)b * S_ + s) * E_ + e];
        y.x += bb.x + xr.x; y.y += bb.y + xr.y;
        y.z += bb.z + xr.z; y.w += bb.w + xr.w;
    }

    float sum = y.x + y.y + y.z + y.w;
    float sq  = y.x * y.x + y.y * y.y + y.z * y.z + y.w * y.w;

#pragma unroll
    for (int o = 16; o > 0; o >>= 1) {
        sum += __shfl_xor_sync(0xFFFFFFFFu, sum, o);
        sq  += __shfl_xor_sync(0xFFFFFFFFu, sq, o);
    }
    __shared__ float ssum[4], ssq[4];
    const int wid = tid >> 5, lane = tid & 31;
    if (lane == 0) { ssum[wid] = sum; ssq[wid] = sq; }
    __syncthreads();
    sum = ssum[0] + ssum[1] + ssum[2] + ssum[3];
    sq  = ssq[0] + ssq[1] + ssq[2] + ssq[3];

    const float mu  = sum * (1.0f / E_);
    const float var = sq * (1.0f / E_) - mu * mu;
    const float inv = rsqrtf(var + 1e-5f);

    const float4 g  = *(const float4*)&gamma[e];
    const float4 bt = *(const float4*)&beta[e];
    float4 o;
    o.x = (y.x - mu) * inv * g.x + bt.x;
    o.y = (y.y - mu) * inv * g.y + bt.y;
    o.z = (y.z - mu) * inv * g.z + bt.z;
    o.w = (y.w - mu) * inv * g.w + bt.w;
    *(float4*)&out[((size_t)b * S_ + s) * E_ + e] = o;
}

// ---------------------------------------------------------------------------
extern "C" void kernel_launch(void* const* d_in, const int* in_sizes, int n_in,
                              void* d_out, int out_size)
{
    const float* x     = (const float*)d_in[0];
    const float* W1    = (const float*)d_in[1];
    const float* b1    = (const float*)d_in[2];
    const float* W2    = (const float*)d_in[3];
    const float* b2    = (const float*)d_in[4];
    const float* gamma = (const float*)d_in[5];
    const float* beta  = (const float*)d_in[6];
    float* out = (float*)d_out;

    gemm1_kernel<<<dim3(F_ / 512, S_), 256>>>(x, W1, b1);
    gemm2_kernel<<<dim3(S_, KSPLIT), 256>>>(W2);
    ln_kernel<<<B_ * S_, 128>>>(x, b2, gamma, beta, out);
}